// round 9
// baseline (speedup 1.0000x reference)
#include <cuda_runtime.h>

// Problem constants
#define BATCH 2
#define SEQ   2048
#define DIM   1024
#define NH    16
#define HD    64
#define MROWS (BATCH * SEQ)   // 4096

// Scratch (allocation-free rule: __device__ globals)
__device__ float g_q[BATCH * NH * SEQ * HD];   // [B,H,S,hd]
__device__ float g_k[BATCH * NH * SEQ * HD];
__device__ float g_v[BATCH * NH * SEQ * HD];
__device__ float g_h[MROWS * DIM];             // [B,S,D] attention output

__device__ __forceinline__ float to_tf32(float x) {
    unsigned u;
    asm("cvt.rna.tf32.f32 %0, %1;" : "=r"(u) : "f"(x));
    return __uint_as_float(u);
}
__device__ __forceinline__ unsigned to_tf32u(float x) {
    unsigned u;
    asm("cvt.rna.tf32.f32 %0, %1;" : "=r"(u) : "f"(x));
    return u;
}

__device__ __forceinline__ void mma_tf32(float* c, const unsigned* a, const unsigned* b) {
    asm volatile(
        "mma.sync.aligned.m16n8k8.row.col.f32.tf32.tf32.f32 "
        "{%0,%1,%2,%3}, {%4,%5,%6,%7}, {%8,%9}, {%0,%1,%2,%3};"
        : "+f"(c[0]), "+f"(c[1]), "+f"(c[2]), "+f"(c[3])
        : "r"(a[0]), "r"(a[1]), "r"(a[2]), "r"(a[3]), "r"(b[0]), "r"(b[1]));
}

// ---------------------------------------------------------------------------
// C = A @ B^T via tf32 mma.sync.  A: [M,K] rm, Bm: [N,K] rm.
// CTA tile 128x128, BK=32, 256 threads = 8 warps (2m x 4n), warp tile 64x32.
// R4 layout (stride 36, cvt at store) + DOUBLE-BUFFERED smem, ONE sync/iter:
//   store(buf); __syncthreads(); prefetch(it+1); compute(buf);
// Dynamic smem 72KB -> 2 CTAs/SM (144KB < 228KB), regs pinned via launch_bounds.
// MODE 0: scatter epilogue into g_q/g_k/g_v; MODE 1: row-major C.
// ---------------------------------------------------------------------------
extern __shared__ float sm_gemm[];

template <int MODE>
__global__ __launch_bounds__(256, 2) void gemm_tf32(const float* __restrict__ A,
                                                    const float* __restrict__ Bm,
                                                    float* __restrict__ C,
                                                    int K, int Nld) {
    float* Asb = sm_gemm;                 // [2][128][36]
    float* Bsb = sm_gemm + 2 * 128 * 36;  // [2][128][36]

    const int tid  = threadIdx.x;
    const int m0   = blockIdx.y * 128;
    const int n0   = blockIdx.x * 128;
    const int warp = tid >> 5;
    const int lane = tid & 31;
    const int wm   = (warp & 1) * 64;
    const int wn   = (warp >> 1) * 32;
    const int g    = lane >> 2;
    const int tg   = lane & 3;

    float acc[4][4][4];
#pragma unroll
    for (int mt = 0; mt < 4; mt++)
#pragma unroll
        for (int nt = 0; nt < 4; nt++)
#pragma unroll
            for (int i = 0; i < 4; i++) acc[mt][nt][i] = 0.0f;

    // gmem tile loads: 128 rows x 32 cols, 16 floats (4 float4) per thread
    const int lrow = tid >> 1;
    const int lcol = (tid & 1) * 16;
    const float* ap = A  + (size_t)(m0 + lrow) * K + lcol;
    const float* bp = Bm + (size_t)(n0 + lrow) * K + lcol;

    float4 pa[4], pb[4];
#pragma unroll
    for (int i = 0; i < 4; i++) { pa[i] = *(const float4*)(ap + i * 4); pb[i] = *(const float4*)(bp + i * 4); }

    const int niter = K >> 5;
    for (int it = 0; it < niter; it++) {
        const int buf = it & 1;
        float* As = Asb + buf * 128 * 36;
        float* Bs = Bsb + buf * 128 * 36;

        // store current tile (convert to tf32 once, reused by all warps)
#pragma unroll
        for (int i = 0; i < 4; i++) {
            float4 a = pa[i], b = pb[i];
            a.x = to_tf32(a.x); a.y = to_tf32(a.y); a.z = to_tf32(a.z); a.w = to_tf32(a.w);
            b.x = to_tf32(b.x); b.y = to_tf32(b.y); b.z = to_tf32(b.z); b.w = to_tf32(b.w);
            *(float4*)&As[lrow * 36 + lcol + i * 4] = a;
            *(float4*)&Bs[lrow * 36 + lcol + i * 4] = b;
        }
        __syncthreads();   // the ONLY sync per iter (double buffer makes it safe)

        // prefetch next tile into registers (latency covered by compute below)
        if (it + 1 < niter) {
            const int ko = (it + 1) << 5;
#pragma unroll
            for (int i = 0; i < 4; i++) {
                pa[i] = *(const float4*)(ap + ko + i * 4);
                pb[i] = *(const float4*)(bp + ko + i * 4);
            }
        }

#pragma unroll
        for (int kt = 0; kt < 4; kt++) {
            const int kc = kt * 8 + tg;
            unsigned fa[4][4], fb[4][2];
#pragma unroll
            for (int mt = 0; mt < 4; mt++) {
                const float* ar = As + (wm + mt * 16 + g) * 36;
                fa[mt][0] = __float_as_uint(ar[kc]);
                fa[mt][1] = __float_as_uint(ar[8 * 36 + kc]);
                fa[mt][2] = __float_as_uint(ar[kc + 4]);
                fa[mt][3] = __float_as_uint(ar[8 * 36 + kc + 4]);
            }
#pragma unroll
            for (int nt = 0; nt < 4; nt++) {
                const float* br = Bs + (wn + nt * 8 + g) * 36;
                fb[nt][0] = __float_as_uint(br[kc]);
                fb[nt][1] = __float_as_uint(br[kc + 4]);
            }
#pragma unroll
            for (int mt = 0; mt < 4; mt++)
#pragma unroll
                for (int nt = 0; nt < 4; nt++)
                    mma_tf32(acc[mt][nt], fa[mt], fb[nt]);
        }
        // no trailing sync: next iter writes the other buffer
    }

    // epilogue: c0=(g,2tg) c1=(g,2tg+1) c2=(g+8,2tg) c3=(g+8,2tg+1)
#pragma unroll
    for (int mt = 0; mt < 4; mt++) {
#pragma unroll
        for (int nt = 0; nt < 4; nt++) {
#pragma unroll
            for (int half = 0; half < 2; half++) {
                const int m = m0 + wm + mt * 16 + g + half * 8;
                const int n = n0 + wn + nt * 8 + tg * 2;
                float2 val = make_float2(acc[mt][nt][half * 2], acc[mt][nt][half * 2 + 1]);
                if (MODE == 0) {
                    const int b = m >> 11;
                    const int s = m & (SEQ - 1);
                    const int sel    = n >> 10;
                    const int within = n & (DIM - 1);
                    const int head   = within >> 6;
                    const int dcol   = within & (HD - 1);
                    const size_t idx = (((size_t)(b * NH + head) * SEQ) + s) * HD + dcol;
                    if (sel == 0)      *(float2*)&g_q[idx] = val;
                    else if (sel == 1) *(float2*)&g_k[idx] = val;
                    else               *(float2*)&g_v[idx] = val;
                } else {
                    *(float2*)&C[(size_t)m * Nld + n] = val;
                }
            }
        }
    }
}

// ---------------------------------------------------------------------------
// Flash attention (causal) on tensor cores.  (identical to R5 passing version)
// ---------------------------------------------------------------------------
__global__ __launch_bounds__(256, 2) void attn_kernel() {
    __shared__ float Ks[32][68];
    __shared__ float Vs[32][72];
    __shared__ float Ss[128][36];

    const int tid  = threadIdx.x;
    const int warp = tid >> 5;
    const int lane = tid & 31;
    const int g    = lane >> 2;
    const int tg   = lane & 3;
    const int wm   = warp * 16;

    const int q0 = ((int)gridDim.x - 1 - (int)blockIdx.x) * 128;
    const int bh = blockIdx.y;
    const int b  = bh >> 4;
    const int h  = bh & 15;

    const float* Qp = g_q + ((size_t)bh * SEQ + q0) * HD;
    const float* Kp = g_k + (size_t)bh * SEQ * HD;
    const float* Vp = g_v + (size_t)bh * SEQ * HD;

    unsigned qf[8][4];
#pragma unroll
    for (int kt = 0; kt < 8; kt++) {
        const int c = kt * 8 + tg;
        qf[kt][0] = to_tf32u(Qp[(size_t)(wm + g)     * HD + c]);
        qf[kt][1] = to_tf32u(Qp[(size_t)(wm + g + 8) * HD + c]);
        qf[kt][2] = to_tf32u(Qp[(size_t)(wm + g)     * HD + c + 4]);
        qf[kt][3] = to_tf32u(Qp[(size_t)(wm + g + 8) * HD + c + 4]);
    }

    float oacc[8][4];
#pragma unroll
    for (int nb = 0; nb < 8; nb++)
#pragma unroll
        for (int i = 0; i < 4; i++) oacc[nb][i] = 0.0f;

    float m0r = -1e30f, m1r = -1e30f, l0r = 0.0f, l1r = 0.0f;

    const int row0 = q0 + wm + g;
    const int row1 = row0 + 8;

    const int lrow = tid >> 3;
    const int lcol = (tid & 7) * 8;

    const int kend = q0 + 128;
    for (int k0 = 0; k0 < kend; k0 += 32) {
        __syncthreads();
        {
            const float* kp = Kp + (size_t)(k0 + lrow) * HD + lcol;
            const float* vp = Vp + (size_t)(k0 + lrow) * HD + lcol;
#pragma unroll
            for (int i = 0; i < 2; i++) {
                float4 kv = *(const float4*)(kp + i * 4);
                float4 vv = *(const float4*)(vp + i * 4);
                kv.x = to_tf32(kv.x); kv.y = to_tf32(kv.y); kv.z = to_tf32(kv.z); kv.w = to_tf32(kv.w);
                vv.x = to_tf32(vv.x); vv.y = to_tf32(vv.y); vv.z = to_tf32(vv.z); vv.w = to_tf32(vv.w);
                *(float4*)&Ks[lrow][lcol + i * 4] = kv;
                *(float4*)&Vs[lrow][lcol + i * 4] = vv;
            }
        }
        __syncthreads();

        float sacc[4][4];
#pragma unroll
        for (int nb = 0; nb < 4; nb++)
#pragma unroll
            for (int i = 0; i < 4; i++) sacc[nb][i] = 0.0f;

#pragma unroll
        for (int kt = 0; kt < 8; kt++) {
            const int kc = kt * 8 + tg;
            unsigned bf[4][2];
#pragma unroll
            for (int nb = 0; nb < 4; nb++) {
                bf[nb][0] = __float_as_uint(Ks[nb * 8 + g][kc]);
                bf[nb][1] = __float_as_uint(Ks[nb * 8 + g][kc + 4]);
            }
#pragma unroll
            for (int nb = 0; nb < 4; nb++)
                mma_tf32(sacc[nb], qf[kt], bf[nb]);
        }

#pragma unroll
        for (int nb = 0; nb < 4; nb++) {
#pragma unroll
            for (int j = 0; j < 2; j++) {
                const int col = k0 + nb * 8 + 2 * tg + j;
                sacc[nb][j]     = (col <= row0) ? sacc[nb][j]     * 0.125f : -1e30f;
                sacc[nb][2 + j] = (col <= row1) ? sacc[nb][2 + j] * 0.125f : -1e30f;
            }
        }

        float mx0 = -1e30f, mx1 = -1e30f;
#pragma unroll
        for (int nb = 0; nb < 4; nb++) {
            mx0 = fmaxf(mx0, fmaxf(sacc[nb][0], sacc[nb][1]));
            mx1 = fmaxf(mx1, fmaxf(sacc[nb][2], sacc[nb][3]));
        }
        mx0 = fmaxf(mx0, __shfl_xor_sync(0xffffffffu, mx0, 1));
        mx0 = fmaxf(mx0, __shfl_xor_sync(0xffffffffu, mx0, 2));
        mx1 = fmaxf(mx1, __shfl_xor_sync(0xffffffffu, mx1, 1));
        mx1 = fmaxf(mx1, __shfl_xor_sync(0xffffffffu, mx1, 2));

        const float mn0 = fmaxf(m0r, mx0);
        const float mn1 = fmaxf(m1r, mx1);
        const float sc0 = __expf(m0r - mn0);
        const float sc1 = __expf(m1r - mn1);

        float ps0 = 0.0f, ps1 = 0.0f;
#pragma unroll
        for (int nb = 0; nb < 4; nb++) {
            const int cc = nb * 8 + 2 * tg;
            float p00 = __expf(sacc[nb][0] - mn0);
            float p01 = __expf(sacc[nb][1] - mn0);
            float p10 = __expf(sacc[nb][2] - mn1);
            float p11 = __expf(sacc[nb][3] - mn1);
            ps0 += p00 + p01;
            ps1 += p10 + p11;
            Ss[wm + g][cc]         = to_tf32(p00);
            Ss[wm + g][cc + 1]     = to_tf32(p01);
            Ss[wm + g + 8][cc]     = to_tf32(p10);
            Ss[wm + g + 8][cc + 1] = to_tf32(p11);
        }
        ps0 += __shfl_xor_sync(0xffffffffu, ps0, 1);
        ps0 += __shfl_xor_sync(0xffffffffu, ps0, 2);
        ps1 += __shfl_xor_sync(0xffffffffu, ps1, 1);
        ps1 += __shfl_xor_sync(0xffffffffu, ps1, 2);
        l0r = l0r * sc0 + ps0;
        l1r = l1r * sc1 + ps1;
        m0r = mn0;
        m1r = mn1;

#pragma unroll
        for (int nb = 0; nb < 8; nb++) {
            oacc[nb][0] *= sc0; oacc[nb][1] *= sc0;
            oacc[nb][2] *= sc1; oacc[nb][3] *= sc1;
        }
        __syncwarp();

#pragma unroll
        for (int kt = 0; kt < 4; kt++) {
            const int kc = kt * 8 + tg;
            unsigned af[4];
            af[0] = __float_as_uint(Ss[wm + g][kc]);
            af[1] = __float_as_uint(Ss[wm + g + 8][kc]);
            af[2] = __float_as_uint(Ss[wm + g][kc + 4]);
            af[3] = __float_as_uint(Ss[wm + g + 8][kc + 4]);
#pragma unroll
            for (int nb = 0; nb < 8; nb++) {
                unsigned bf2[2];
                bf2[0] = __float_as_uint(Vs[kc][nb * 8 + g]);
                bf2[1] = __float_as_uint(Vs[kc + 4][nb * 8 + g]);
                mma_tf32(oacc[nb], af, bf2);
            }
        }
    }

    const float inv0 = 1.0f / l0r;
    const float inv1 = 1.0f / l1r;
    float* out0 = g_h + ((size_t)b * SEQ + row0) * DIM + h * HD;
    float* out1 = g_h + ((size_t)b * SEQ + row1) * DIM + h * HD;
#pragma unroll
    for (int nb = 0; nb < 8; nb++) {
        const int cc = nb * 8 + 2 * tg;
        *(float2*)(out0 + cc) = make_float2(oacc[nb][0] * inv0, oacc[nb][1] * inv0);
        *(float2*)(out1 + cc) = make_float2(oacc[nb][2] * inv1, oacc[nb][3] * inv1);
    }
}

// ---------------------------------------------------------------------------
extern "C" void kernel_launch(void* const* d_in, const int* in_sizes, int n_in,
                              void* d_out, int out_size) {
    const float* x     = (const float*)d_in[0];   // [B,S,D]
    const float* w_qkv = (const float*)d_in[1];   // [3D, D]
    const float* w_o   = (const float*)d_in[2];   // [D, D]
    float* out = (float*)d_out;                   // [B,S,D]

    const int GEMM_SMEM = 4 * 128 * 36 * 4;   // 73728 B (double-buffered A+B)
    cudaFuncSetAttribute(gemm_tf32<0>, cudaFuncAttributeMaxDynamicSharedMemorySize, GEMM_SMEM);
    cudaFuncSetAttribute(gemm_tf32<1>, cudaFuncAttributeMaxDynamicSharedMemorySize, GEMM_SMEM);

    // QKV projection: [4096,1024] @ [3072,1024]^T, scatter to q/k/v (tf32 mma)
    gemm_tf32<0><<<dim3(3 * DIM / 128, MROWS / 128), 256, GEMM_SMEM>>>(x, w_qkv, nullptr, DIM, 0);

    // Causal flash attention (tensor cores) -> g_h [B,S,D]
    attn_kernel<<<dim3(SEQ / 128, BATCH * NH), 256>>>();

    // Output projection: [4096,1024] @ [1024,1024]^T -> d_out (tf32 mma)
    float* hptr = nullptr;
    cudaGetSymbolAddress((void**)&hptr, g_h);
    gemm_tf32<1><<<dim3(DIM / 128, MROWS / 128), 256, GEMM_SMEM>>>(hptr, w_o, out, DIM, DIM);
}

// round 11
// speedup vs baseline: 1.0529x; 1.0529x over previous
#include <cuda_runtime.h>

// Problem constants
#define BATCH 2
#define SEQ   2048
#define DIM   1024
#define NH    16
#define HD    64
#define MROWS (BATCH * SEQ)   // 4096

// Scratch (allocation-free rule: __device__ globals)
__device__ float g_q[BATCH * NH * SEQ * HD];   // [B,H,S,hd]
__device__ float g_k[BATCH * NH * SEQ * HD];
__device__ float g_v[BATCH * NH * SEQ * HD];
__device__ float g_h[MROWS * DIM];             // [B,S,D] attention output

__device__ __forceinline__ float to_tf32(float x) {
    unsigned u;
    asm("cvt.rna.tf32.f32 %0, %1;" : "=r"(u) : "f"(x));
    return __uint_as_float(u);
}
__device__ __forceinline__ unsigned to_tf32u(float x) {
    unsigned u;
    asm("cvt.rna.tf32.f32 %0, %1;" : "=r"(u) : "f"(x));
    return u;
}

__device__ __forceinline__ void mma_tf32(float* c, const unsigned* a, const unsigned* b) {
    asm volatile(
        "mma.sync.aligned.m16n8k8.row.col.f32.tf32.tf32.f32 "
        "{%0,%1,%2,%3}, {%4,%5,%6,%7}, {%8,%9}, {%0,%1,%2,%3};"
        : "+f"(c[0]), "+f"(c[1]), "+f"(c[2]), "+f"(c[3])
        : "r"(a[0]), "r"(a[1]), "r"(a[2]), "r"(a[3]), "r"(b[0]), "r"(b[1]));
}

__device__ __forceinline__ void cp16(float* dst_smem, const float* src) {
    unsigned d = (unsigned)__cvta_generic_to_shared(dst_smem);
    asm volatile("cp.async.cg.shared.global [%0], [%1], 16;\n" :: "r"(d), "l"(src));
}

// ---------------------------------------------------------------------------
// C = A @ B^T via tf32 mma.sync.  (byte-exact R4 version — best measured)
// CTA tile 128x128, BK=32, 256 threads = 8 warps (2m x 4n), warp tile 64x32.
// ---------------------------------------------------------------------------
template <int MODE>
__global__ __launch_bounds__(256) void gemm_tf32(const float* __restrict__ A,
                                                 const float* __restrict__ Bm,
                                                 float* __restrict__ C,
                                                 int K, int Nld) {
    __shared__ float As[128][36];   // padded: 36r mod 32 -> conflict-free frags
    __shared__ float Bs[128][36];

    const int tid  = threadIdx.x;
    const int m0   = blockIdx.y * 128;
    const int n0   = blockIdx.x * 128;
    const int warp = tid >> 5;
    const int lane = tid & 31;
    const int wm   = (warp & 1) * 64;
    const int wn   = (warp >> 1) * 32;
    const int g    = lane >> 2;
    const int tg   = lane & 3;

    float acc[4][4][4];
#pragma unroll
    for (int mt = 0; mt < 4; mt++)
#pragma unroll
        for (int nt = 0; nt < 4; nt++)
#pragma unroll
            for (int i = 0; i < 4; i++) acc[mt][nt][i] = 0.0f;

    const int lrow = tid >> 1;
    const int lcol = (tid & 1) * 16;
    const float* ap = A  + (size_t)(m0 + lrow) * K + lcol;
    const float* bp = Bm + (size_t)(n0 + lrow) * K + lcol;

    float4 pa[4], pb[4];
#pragma unroll
    for (int i = 0; i < 4; i++) { pa[i] = *(const float4*)(ap + i * 4); pb[i] = *(const float4*)(bp + i * 4); }

    for (int k0 = 0; k0 < K; k0 += 32) {
#pragma unroll
        for (int i = 0; i < 4; i++) {
            float4 a = pa[i], b = pb[i];
            a.x = to_tf32(a.x); a.y = to_tf32(a.y); a.z = to_tf32(a.z); a.w = to_tf32(a.w);
            b.x = to_tf32(b.x); b.y = to_tf32(b.y); b.z = to_tf32(b.z); b.w = to_tf32(b.w);
            *(float4*)&As[lrow][lcol + i * 4] = a;
            *(float4*)&Bs[lrow][lcol + i * 4] = b;
        }
        __syncthreads();

        if (k0 + 32 < K) {
#pragma unroll
            for (int i = 0; i < 4; i++) {
                pa[i] = *(const float4*)(ap + k0 + 32 + i * 4);
                pb[i] = *(const float4*)(bp + k0 + 32 + i * 4);
            }
        }

#pragma unroll
        for (int kt = 0; kt < 4; kt++) {
            const int kc = kt * 8 + tg;
            unsigned fa[4][4], fb[4][2];
#pragma unroll
            for (int mt = 0; mt < 4; mt++) {
                const int r = wm + mt * 16 + g;
                fa[mt][0] = __float_as_uint(As[r][kc]);
                fa[mt][1] = __float_as_uint(As[r + 8][kc]);
                fa[mt][2] = __float_as_uint(As[r][kc + 4]);
                fa[mt][3] = __float_as_uint(As[r + 8][kc + 4]);
            }
#pragma unroll
            for (int nt = 0; nt < 4; nt++) {
                const int r = wn + nt * 8 + g;
                fb[nt][0] = __float_as_uint(Bs[r][kc]);
                fb[nt][1] = __float_as_uint(Bs[r][kc + 4]);
            }
#pragma unroll
            for (int mt = 0; mt < 4; mt++)
#pragma unroll
                for (int nt = 0; nt < 4; nt++)
                    mma_tf32(acc[mt][nt], fa[mt], fb[nt]);
        }
        __syncthreads();
    }

#pragma unroll
    for (int mt = 0; mt < 4; mt++) {
#pragma unroll
        for (int nt = 0; nt < 4; nt++) {
#pragma unroll
            for (int half = 0; half < 2; half++) {
                const int m = m0 + wm + mt * 16 + g + half * 8;
                const int n = n0 + wn + nt * 8 + tg * 2;
                float2 val = make_float2(acc[mt][nt][half * 2], acc[mt][nt][half * 2 + 1]);
                if (MODE == 0) {
                    const int b = m >> 11;
                    const int s = m & (SEQ - 1);
                    const int sel    = n >> 10;
                    const int within = n & (DIM - 1);
                    const int head   = within >> 6;
                    const int dcol   = within & (HD - 1);
                    const size_t idx = (((size_t)(b * NH + head) * SEQ) + s) * HD + dcol;
                    if (sel == 0)      *(float2*)&g_q[idx] = val;
                    else if (sel == 1) *(float2*)&g_k[idx] = val;
                    else               *(float2*)&g_v[idx] = val;
                } else {
                    *(float2*)&C[(size_t)m * Nld + n] = val;
                }
            }
        }
    }
}

// ---------------------------------------------------------------------------
// Flash attention (causal) on tensor cores, cp.async 2-stage K/V pipeline.
// Q tile 128 (8 warps x 16 rows), K tile 32, hd=64.
// K/V in raw fp32 double buffers (cp.async); tf32 cvt at fragment load
// (bitwise identical numerics to cvt-at-store). ONE __syncthreads per iter.
// Dynamic smem (53KB) — 2 CTAs/SM.
// Layout within dynamic block (floats):
//   Ks[2][32][68]  @ 0        (4352)
//   Vs[2][32][72]  @ 4352     (4608)
//   Ss[128][36]    @ 8960     (4608)   total 13568 floats = 54272 B
// ---------------------------------------------------------------------------
#define ATTN_SMEM_FLOATS (2 * 32 * 68 + 2 * 32 * 72 + 128 * 36)

extern __shared__ float sm_attn[];

__global__ __launch_bounds__(256, 2) void attn_kernel() {
    float* KsBase = sm_attn;                  // [2][32][68]
    float* VsBase = sm_attn + 2 * 32 * 68;    // [2][32][72]
    float* SsBase = VsBase + 2 * 32 * 72;     // [128][36]

    const int tid  = threadIdx.x;
    const int warp = tid >> 5;
    const int lane = tid & 31;
    const int g    = lane >> 2;
    const int tg   = lane & 3;
    const int wm   = warp * 16;

    const int q0 = ((int)gridDim.x - 1 - (int)blockIdx.x) * 128;  // big tiles first
    const int bh = blockIdx.y;
    const int b  = bh >> 4;
    const int h  = bh & 15;

    const float* Qp = g_q + ((size_t)bh * SEQ + q0) * HD;
    const float* Kp = g_k + (size_t)bh * SEQ * HD;
    const float* Vp = g_v + (size_t)bh * SEQ * HD;

    unsigned qf[8][4];
#pragma unroll
    for (int kt = 0; kt < 8; kt++) {
        const int c = kt * 8 + tg;
        qf[kt][0] = to_tf32u(Qp[(size_t)(wm + g)     * HD + c]);
        qf[kt][1] = to_tf32u(Qp[(size_t)(wm + g + 8) * HD + c]);
        qf[kt][2] = to_tf32u(Qp[(size_t)(wm + g)     * HD + c + 4]);
        qf[kt][3] = to_tf32u(Qp[(size_t)(wm + g + 8) * HD + c + 4]);
    }

    float oacc[8][4];
#pragma unroll
    for (int nb = 0; nb < 8; nb++)
#pragma unroll
        for (int i = 0; i < 4; i++) oacc[nb][i] = 0.0f;

    float m0r = -1e30f, m1r = -1e30f, l0r = 0.0f, l1r = 0.0f;

    const int row0 = q0 + wm + g;
    const int row1 = row0 + 8;

    // K/V loader mapping: 32x64 floats, 2 float4 each for K and V per thread
    const int lrow = tid >> 3;           // 0..31
    const int lcol = (tid & 7) * 8;      // 0..56

    const int niter = (q0 + 128) >> 5;

    // prologue: issue tile 0
    {
        const float* kp = Kp + (size_t)lrow * HD + lcol;
        const float* vp = Vp + (size_t)lrow * HD + lcol;
        cp16(KsBase + lrow * 68 + lcol, kp);
        cp16(KsBase + lrow * 68 + lcol + 4, kp + 4);
        cp16(VsBase + lrow * 72 + lcol, vp);
        cp16(VsBase + lrow * 72 + lcol + 4, vp + 4);
        asm volatile("cp.async.commit_group;\n");
    }

    for (int it = 0; it < niter; it++) {
        const int buf = it & 1;
        float* Ks = KsBase + buf * 32 * 68;
        float* Vs = VsBase + buf * 32 * 72;
        asm volatile("cp.async.wait_group 0;\n");
        __syncthreads();   // tile `it` visible to all; compute(it-1) done by all

        // issue tile it+1 into the other buffer (overlaps compute below)
        if (it + 1 < niter) {
            float* Kn = KsBase + (1 - buf) * 32 * 68;
            float* Vn = VsBase + (1 - buf) * 32 * 72;
            const float* kp = Kp + (size_t)((it + 1) * 32 + lrow) * HD + lcol;
            const float* vp = Vp + (size_t)((it + 1) * 32 + lrow) * HD + lcol;
            cp16(Kn + lrow * 68 + lcol, kp);
            cp16(Kn + lrow * 68 + lcol + 4, kp + 4);
            cp16(Vn + lrow * 72 + lcol, vp);
            cp16(Vn + lrow * 72 + lcol + 4, vp + 4);
            asm volatile("cp.async.commit_group;\n");
        }

        const int k0 = it << 5;

        // S = Q @ K^T  (16 x 32 per warp); K cvt to tf32 at fragment load
        float sacc[4][4];
#pragma unroll
        for (int nb = 0; nb < 4; nb++)
#pragma unroll
            for (int i = 0; i < 4; i++) sacc[nb][i] = 0.0f;

#pragma unroll
        for (int kt = 0; kt < 8; kt++) {
            const int kc = kt * 8 + tg;
            unsigned bf[4][2];
#pragma unroll
            for (int nb = 0; nb < 4; nb++) {
                bf[nb][0] = to_tf32u(Ks[(nb * 8 + g) * 68 + kc]);
                bf[nb][1] = to_tf32u(Ks[(nb * 8 + g) * 68 + kc + 4]);
            }
#pragma unroll
            for (int nb = 0; nb < 4; nb++)
                mma_tf32(sacc[nb], qf[kt], bf[nb]);
        }

        // mask + scale (1/8)
#pragma unroll
        for (int nb = 0; nb < 4; nb++) {
#pragma unroll
            for (int j = 0; j < 2; j++) {
                const int col = k0 + nb * 8 + 2 * tg + j;
                sacc[nb][j]     = (col <= row0) ? sacc[nb][j]     * 0.125f : -1e30f;
                sacc[nb][2 + j] = (col <= row1) ? sacc[nb][2 + j] * 0.125f : -1e30f;
            }
        }

        float mx0 = -1e30f, mx1 = -1e30f;
#pragma unroll
        for (int nb = 0; nb < 4; nb++) {
            mx0 = fmaxf(mx0, fmaxf(sacc[nb][0], sacc[nb][1]));
            mx1 = fmaxf(mx1, fmaxf(sacc[nb][2], sacc[nb][3]));
        }
        mx0 = fmaxf(mx0, __shfl_xor_sync(0xffffffffu, mx0, 1));
        mx0 = fmaxf(mx0, __shfl_xor_sync(0xffffffffu, mx0, 2));
        mx1 = fmaxf(mx1, __shfl_xor_sync(0xffffffffu, mx1, 1));
        mx1 = fmaxf(mx1, __shfl_xor_sync(0xffffffffu, mx1, 2));

        const float mn0 = fmaxf(m0r, mx0);
        const float mn1 = fmaxf(m1r, mx1);
        const float sc0 = __expf(m0r - mn0);
        const float sc1 = __expf(m1r - mn1);

        float ps0 = 0.0f, ps1 = 0.0f;
        float* SsW = SsBase + (wm + g) * 36;
#pragma unroll
        for (int nb = 0; nb < 4; nb++) {
            const int cc = nb * 8 + 2 * tg;
            float p00 = __expf(sacc[nb][0] - mn0);
            float p01 = __expf(sacc[nb][1] - mn0);
            float p10 = __expf(sacc[nb][2] - mn1);
            float p11 = __expf(sacc[nb][3] - mn1);
            ps0 += p00 + p01;
            ps1 += p10 + p11;
            SsW[cc]            = to_tf32(p00);
            SsW[cc + 1]        = to_tf32(p01);
            SsW[8 * 36 + cc]     = to_tf32(p10);
            SsW[8 * 36 + cc + 1] = to_tf32(p11);
        }
        ps0 += __shfl_xor_sync(0xffffffffu, ps0, 1);
        ps0 += __shfl_xor_sync(0xffffffffu, ps0, 2);
        ps1 += __shfl_xor_sync(0xffffffffu, ps1, 1);
        ps1 += __shfl_xor_sync(0xffffffffu, ps1, 2);
        l0r = l0r * sc0 + ps0;
        l1r = l1r * sc1 + ps1;
        m0r = mn0;
        m1r = mn1;

#pragma unroll
        for (int nb = 0; nb < 8; nb++) {
            oacc[nb][0] *= sc0; oacc[nb][1] *= sc0;
            oacc[nb][2] *= sc1; oacc[nb][3] *= sc1;
        }
        __syncwarp();   // Ss region is warp-private

        // O += P @ V ; V cvt to tf32 at fragment load
#pragma unroll
        for (int kt = 0; kt < 4; kt++) {
            const int kc = kt * 8 + tg;
            unsigned af[4];
            af[0] = __float_as_uint(SsW[kc]);
            af[1] = __float_as_uint(SsW[8 * 36 + kc]);
            af[2] = __float_as_uint(SsW[kc + 4]);
            af[3] = __float_as_uint(SsW[8 * 36 + kc + 4]);
#pragma unroll
            for (int nb = 0; nb < 8; nb++) {
                unsigned bf2[2];
                bf2[0] = to_tf32u(Vs[kc * 72 + nb * 8 + g]);
                bf2[1] = to_tf32u(Vs[(kc + 4) * 72 + nb * 8 + g]);
                mma_tf32(oacc[nb], af, bf2);
            }
        }
    }

    const float inv0 = 1.0f / l0r;
    const float inv1 = 1.0f / l1r;
    float* out0 = g_h + ((size_t)b * SEQ + row0) * DIM + h * HD;
    float* out1 = g_h + ((size_t)b * SEQ + row1) * DIM + h * HD;
#pragma unroll
    for (int nb = 0; nb < 8; nb++) {
        const int cc = nb * 8 + 2 * tg;
        *(float2*)(out0 + cc) = make_float2(oacc[nb][0] * inv0, oacc[nb][1] * inv0);
        *(float2*)(out1 + cc) = make_float2(oacc[nb][2] * inv1, oacc[nb][3] * inv1);
    }
}

// ---------------------------------------------------------------------------
extern "C" void kernel_launch(void* const* d_in, const int* in_sizes, int n_in,
                              void* d_out, int out_size) {
    const float* x     = (const float*)d_in[0];   // [B,S,D]
    const float* w_qkv = (const float*)d_in[1];   // [3D, D]
    const float* w_o   = (const float*)d_in[2];   // [D, D]
    float* out = (float*)d_out;                   // [B,S,D]

    const int ATTN_SMEM = ATTN_SMEM_FLOATS * 4;   // 54272 B
    cudaFuncSetAttribute(attn_kernel, cudaFuncAttributeMaxDynamicSharedMemorySize, ATTN_SMEM);

    // QKV projection: [4096,1024] @ [3072,1024]^T, scatter to q/k/v (tf32 mma)
    gemm_tf32<0><<<dim3(3 * DIM / 128, MROWS / 128), 256>>>(x, w_qkv, nullptr, DIM, 0);

    // Causal flash attention (tensor cores, cp.async pipeline) -> g_h [B,S,D]
    attn_kernel<<<dim3(SEQ / 128, BATCH * NH), 256, ATTN_SMEM>>>();

    // Output projection: [4096,1024] @ [1024,1024]^T -> d_out (tf32 mma)
    float* hptr = nullptr;
    cudaGetSymbolAddress((void**)&hptr, g_h);
    gemm_tf32<1><<<dim3(DIM / 128, MROWS / 128), 256>>>(hptr, w_o, out, DIM, DIM);
}